// round 3
// baseline (speedup 1.0000x reference)
#include <cuda_runtime.h>

#define NSV  20
#define BSZ  256
#define SSZ  1000
#define TST  999

typedef unsigned long long ull;

// statevar scratch: [B][S][NSV]
__device__ float g_sv[BSZ * SSZ * NSV];

__device__ __forceinline__ ull pk(float lo, float hi) {
    ull r; asm("mov.b64 %0,{%1,%2};" : "=l"(r) : "f"(lo), "f"(hi)); return r;
}
__device__ __forceinline__ void fma2(ull &a, ull x, ull y) {
    asm("fma.rn.f32x2 %0,%1,%2,%3;" : "=l"(a) : "l"(x), "l"(y), "l"(a));
}
__device__ __forceinline__ float psum(ull a) {
    float lo, hi; asm("mov.b64 {%0,%1},%2;" : "=f"(lo), "=f"(hi) : "l"(a)); return lo + hi;
}
__device__ __forceinline__ float selu_f(float x) {
    const float s  = 1.0507009873554805f;
    const float sa = 1.7580993408473766f;  // scale * alpha
    float e = __expf(x);
    return x > 0.f ? s * x : sa * e - sa;
}

// ---------------------------------------------------------------------------
// G kernel: recurrent statevar evolution. 128 CTAs x 256 threads.
// Each CTA owns 2 batch chains, pipelined across two thread groups:
//   X = tid [0,128): holds gw0 row + gw1 row in regs; computes L0+L1
//   Y = tid [128,256): holds gw2 row + gw3 slice in regs; computes L2+L3+sv
// ---------------------------------------------------------------------------
__global__ void __launch_bounds__(256, 1) g_kernel(
    const float* __restrict__ x,
    const float* __restrict__ gw0, const float* __restrict__ gb0,
    const float* __restrict__ gw1, const float* __restrict__ gb1,
    const float* __restrict__ gw2, const float* __restrict__ gb2,
    const float* __restrict__ gw3, const float* __restrict__ gb3)
{
    extern __shared__ float sm[];
    float* s_eps = sm;                 // 2 * 999 * 6 = 11988
    float* s_dt  = sm + 11988;         // 2 * 999   = 1998
    float* s_h0  = sm + 13986;         // 128
    float* s_h1  = sm + 14114;         // 2 * 128
    float* s_h2  = sm + 14370;         // 128
    float* s_sv  = sm + 14498;         // 2 * 20
    // total 14538 floats

    const int tid = threadIdx.x;
    const int bid = blockIdx.x;
    const int b0g = 2 * bid;

    // preload strain (eps) and dt for both chains
    for (int i = tid; i < 2 * TST * 6; i += 256) {
        int e = i / (TST * 6);
        int r = i - e * (TST * 6);
        int t = r / 6, f = r - t * 6;
        s_eps[i] = x[(size_t)(b0g + e) * (SSZ * 13) + t * 13 + 1 + f];
    }
    for (int i = tid; i < 2 * TST; i += 256) {
        int e = i / TST, t = i - e * TST;
        const float* xb = x + (size_t)(b0g + e) * (SSZ * 13);
        s_dt[i] = xb[(t + 1) * 13] - xb[t * 13];
    }
    if (tid < 2 * NSV) {
        int e = tid / NSV, o = tid - e * NSV;
        s_sv[tid] = 0.f;
        g_sv[(size_t)(b0g + e) * (SSZ * NSV) + o] = 0.f;  // statevar[:,0,:] = 0
    }
    __syncthreads();

    if (tid < 128) {
        // ------------- group X: L0 + L1 -------------
        const int j = tid;
        ull w0p[13], w1p[64];
        #pragma unroll
        for (int i = 0; i < 13; i++) {
            float2 v = *(const float2*)(gw0 + j * 26 + 2 * i);
            w0p[i] = pk(v.x, v.y);
        }
        #pragma unroll
        for (int i = 0; i < 64; i++) {
            float2 v = *(const float2*)(gw1 + j * 128 + 2 * i);
            w1p[i] = pk(v.x, v.y);
        }
        const float b0 = gb0[j], b1 = gb1[j];

        for (int n = 0; n < 2 * TST + 1; ++n) {
            if (n < 2 * TST) {
                const int e = n & 1, t = n >> 1;
                const ull* ep = (const ull*)(s_eps + e * (TST * 6) + t * 6);
                const ull* sp = (const ull*)(s_sv + e * NSV);
                ull aa = pk(b0, 0.f), ab = 0ull;
                fma2(aa, w0p[0], ep[0]);
                fma2(ab, w0p[1], ep[1]);
                fma2(aa, w0p[2], ep[2]);
                #pragma unroll
                for (int i = 0; i < 10; i += 2) {
                    fma2(ab, w0p[3 + i], sp[i]);
                    fma2(aa, w0p[4 + i], sp[i + 1]);
                }
                s_h0[j] = selu_f(psum(aa) + psum(ab));
                asm volatile("bar.sync 1, 128;" ::: "memory");
                const ull* hp = (const ull*)s_h0;
                ull ca = pk(b1, 0.f), cb = 0ull;
                #pragma unroll
                for (int i = 0; i < 64; i += 2) {
                    fma2(ca, w1p[i],     hp[i]);
                    fma2(cb, w1p[i + 1], hp[i + 1]);
                }
                s_h1[e * 128 + j] = selu_f(psum(ca) + psum(cb));
            }
            asm volatile("bar.sync 0;" ::: "memory");
        }
    } else {
        // ------------- group Y: L2 + L3 + sv update -------------
        const int j  = tid - 128;
        const int oc = j >> 2;
        const int o  = (oc < NSV) ? oc : 0;
        const int p  = j & 3;
        const bool act = (p == 0) && (oc < NSV);
        ull w2p[64], w3p[16];
        #pragma unroll
        for (int i = 0; i < 64; i++) {
            float2 v = *(const float2*)(gw2 + j * 128 + 2 * i);
            w2p[i] = pk(v.x, v.y);
        }
        #pragma unroll
        for (int i = 0; i < 16; i++) {
            float2 v = *(const float2*)(gw3 + o * 128 + p * 32 + 2 * i);
            w3p[i] = pk(v.x, v.y);
        }
        const float b2 = gb2[j], b3 = gb3[o];

        for (int n = 0; n < 2 * TST + 1; ++n) {
            if (n >= 1) {
                const int e = (n - 1) & 1, t = (n - 1) >> 1;
                const ull* hp = (const ull*)(s_h1 + e * 128);
                ull ca = pk(b2, 0.f), cb = 0ull;
                #pragma unroll
                for (int i = 0; i < 64; i += 2) {
                    fma2(ca, w2p[i],     hp[i]);
                    fma2(cb, w2p[i + 1], hp[i + 1]);
                }
                s_h2[j] = selu_f(psum(ca) + psum(cb));
                asm volatile("bar.sync 2, 128;" ::: "memory");
                const ull* h2p = (const ull*)(s_h2 + p * 32);
                ull da = 0ull, db = 0ull;
                #pragma unroll
                for (int i = 0; i < 16; i += 2) {
                    fma2(da, w3p[i],     h2p[i]);
                    fma2(db, w3p[i + 1], h2p[i + 1]);
                }
                float v = psum(da) + psum(db);
                v += __shfl_down_sync(0xffffffffu, v, 1);
                v += __shfl_down_sync(0xffffffffu, v, 2);
                if (act) {
                    float svd = v + b3;
                    float nsv = s_sv[e * NSV + o] + s_dt[e * TST + t] * svd;
                    s_sv[e * NSV + o] = nsv;
                    g_sv[(size_t)(b0g + e) * (SSZ * NSV) + (t + 1) * NSV + o] = nsv;
                }
            }
            asm volatile("bar.sync 0;" ::: "memory");
        }
    }
}

// ---------------------------------------------------------------------------
// F kernel: fused 32->256->256->256->6 MLP over 256000 rows.
// 64 rows per CTA, 256 threads. Each thread computes a 4x16 output micro-tile.
// All FMA operands arrive pre-packed via LDS.64 (k-pairs) -> pure f32x2 math.
// ---------------------------------------------------------------------------
#define FSTR 258
#define WSTR 34

__device__ __forceinline__ void mlayer(
    const float* sIn, float* sOut, float* sW, float* sb,
    const float* __restrict__ Wg, const float* __restrict__ bg,
    int K, int tid)
{
    const int rb = (tid >> 4) * 4;
    const int m  = tid & 15;
    ull acc[4][16];
    #pragma unroll
    for (int r = 0; r < 4; r++)
        #pragma unroll
        for (int c = 0; c < 16; c++) acc[r][c] = 0ull;

    for (int c0 = 0; c0 < K; c0 += 32) {
        __syncthreads();
        if (c0 == 0) sb[tid] = bg[tid];
        // stage W[c][c0 .. c0+31] into sW[c][0..31], stride 34 (conflict-free pairs)
        for (int it = tid; it < 2048; it += 256) {
            int c = it >> 3, q = it & 7;
            float4 v = *(const float4*)(Wg + c * K + c0 + 4 * q);
            float2* d = (float2*)(sW + c * WSTR + 4 * q);
            d[0] = make_float2(v.x, v.y);
            d[1] = make_float2(v.z, v.w);
        }
        __syncthreads();
        const ull* ap0 = (const ull*)(sIn + (rb + 0) * FSTR + c0);
        const ull* ap1 = (const ull*)(sIn + (rb + 1) * FSTR + c0);
        const ull* ap2 = (const ull*)(sIn + (rb + 2) * FSTR + c0);
        const ull* ap3 = (const ull*)(sIn + (rb + 3) * FSTR + c0);
        #pragma unroll
        for (int i = 0; i < 16; ++i) {
            ull a0 = ap0[i], a1 = ap1[i], a2 = ap2[i], a3 = ap3[i];
            #pragma unroll
            for (int ci = 0; ci < 16; ++ci) {
                ull w = *(const ull*)(sW + (m + 16 * ci) * WSTR + 2 * i);
                fma2(acc[0][ci], a0, w);
                fma2(acc[1][ci], a1, w);
                fma2(acc[2][ci], a2, w);
                fma2(acc[3][ci], a3, w);
            }
        }
    }
    #pragma unroll
    for (int r = 0; r < 4; r++) {
        #pragma unroll
        for (int ci = 0; ci < 16; ci++) {
            int c = m + 16 * ci;
            float v = psum(acc[r][ci]) + sb[c];
            sOut[(rb + r) * FSTR + c] = selu_f(v);
        }
    }
}

__global__ void __launch_bounds__(256, 1) f_kernel(
    const float* __restrict__ x,
    const float* __restrict__ fw0, const float* __restrict__ fb0,
    const float* __restrict__ fw1, const float* __restrict__ fb1,
    const float* __restrict__ fw2, const float* __restrict__ fb2,
    const float* __restrict__ fw3, const float* __restrict__ fb3,
    float* __restrict__ out)
{
    extern __shared__ float sm[];
    float* sA  = sm;            // 64 * 258 = 16512
    float* sB  = sm + 16512;    // 16512
    float* sW  = sm + 33024;    // 256 * 34 = 8704
    float* sW3 = sm + 41728;    // 6 * 258 = 1548
    float* sb  = sm + 43276;    // 256
    // total 43532 floats = 174128 B

    const int tid  = threadIdx.x;
    const int row0 = blockIdx.x * 64;

    // stage input rows: [strain(6), strain_dot(6), statevar(20)]
    for (int i = tid; i < 64 * 12; i += 256) {
        int r = i / 12, f = i - r * 12;
        sA[r * FSTR + f] = x[(size_t)(row0 + r) * 13 + 1 + f];
    }
    for (int i = tid; i < 64 * 20; i += 256) {
        int r = i / 20, f = i - r * 20;
        sA[r * FSTR + 12 + f] = g_sv[(size_t)(row0 + r) * 20 + f];
    }
    // stage W3 (6 x 256), stride 258
    for (int i = tid; i < 6 * 64; i += 256) {
        int c = i >> 6, q = i & 63;
        float4 v = *(const float4*)(fw3 + c * 256 + 4 * q);
        float2* d = (float2*)(sW3 + c * FSTR + 4 * q);
        d[0] = make_float2(v.x, v.y);
        d[1] = make_float2(v.z, v.w);
    }

    mlayer(sA, sB, sW, sb, fw0, fb0, 32,  tid);
    mlayer(sB, sA, sW, sb, fw1, fb1, 256, tid);
    mlayer(sA, sB, sW, sb, fw2, fb2, 256, tid);
    __syncthreads();

    // final layer: 6 outputs per row, split-k over 4 lanes
    const int r = tid >> 2, p = tid & 3;
    ull a3[6];
    #pragma unroll
    for (int c = 0; c < 6; c++) a3[c] = 0ull;
    const ull* ap = (const ull*)(sB + r * FSTR + 64 * p);
    #pragma unroll
    for (int i = 0; i < 32; ++i) {
        ull a = ap[i];
        #pragma unroll
        for (int c = 0; c < 6; c++) {
            ull w = *(const ull*)(sW3 + c * FSTR + 64 * p + 2 * i);
            fma2(a3[c], a, w);
        }
    }
    #pragma unroll
    for (int c = 0; c < 6; c++) {
        float v = psum(a3[c]);
        v += __shfl_down_sync(0xffffffffu, v, 1);
        v += __shfl_down_sync(0xffffffffu, v, 2);
        if (p == 0) out[(size_t)(row0 + r) * 6 + c] = v + fb3[c];
    }
}

// ---------------------------------------------------------------------------
extern "C" void kernel_launch(void* const* d_in, const int* in_sizes, int n_in,
                              void* d_out, int out_size)
{
    (void)in_sizes; (void)n_in; (void)out_size;
    const float* x   = (const float*)d_in[0];
    const float* gw0 = (const float*)d_in[1];
    const float* gb0 = (const float*)d_in[2];
    const float* gw1 = (const float*)d_in[3];
    const float* gb1 = (const float*)d_in[4];
    const float* gw2 = (const float*)d_in[5];
    const float* gb2 = (const float*)d_in[6];
    const float* gw3 = (const float*)d_in[7];
    const float* gb3 = (const float*)d_in[8];
    const float* fw0 = (const float*)d_in[9];
    const float* fb0 = (const float*)d_in[10];
    const float* fw1 = (const float*)d_in[11];
    const float* fb1 = (const float*)d_in[12];
    const float* fw2 = (const float*)d_in[13];
    const float* fb2 = (const float*)d_in[14];
    const float* fw3 = (const float*)d_in[15];
    const float* fb3 = (const float*)d_in[16];

    const size_t gsm = 14538 * sizeof(float);
    const size_t fsm = 43532 * sizeof(float);
    cudaFuncSetAttribute(g_kernel, cudaFuncAttributeMaxDynamicSharedMemorySize, (int)gsm);
    cudaFuncSetAttribute(f_kernel, cudaFuncAttributeMaxDynamicSharedMemorySize, (int)fsm);

    g_kernel<<<128, 256, gsm>>>(x, gw0, gb0, gw1, gb1, gw2, gb2, gw3, gb3);
    f_kernel<<<4000, 256, fsm>>>(x, fw0, fb0, fw1, fb1, fw2, fb2, fw3, fb3,
                                 (float*)d_out);
}

// round 9
// speedup vs baseline: 1.6416x; 1.6416x over previous
#include <cuda_runtime.h>
#include <cuda_bf16.h>

#define NSV  20
#define BSZ  256
#define SSZ  1000
#define TST  999

typedef unsigned long long ull;
typedef unsigned int u32;

// tcgen05 is arch-SPECIFIC: only present when compiling the sm_103a/sm_100a
// target. The harness also emits a plain compute_103 PTX pass where these
// instructions are illegal -> guard and provide an fp32 fallback there.
#if defined(__CUDA_ARCH_FEAT_SM103_ALL) || defined(__CUDA_ARCH_FEAT_SM100_ALL) || defined(__CUDA_ARCH_FEAT_SM101_ALL)
#define USE_TC 1
#else
#define USE_TC 0
#endif

// statevar scratch: [B][S][NSV]
__device__ float g_sv[BSZ * SSZ * NSV];
// pre-swizzled bf16 hi/lo weight images: hi at [0,303104), lo at +303104
__device__ __align__(16) unsigned char g_wb[606208];

#define WB_LO_OFF 303104

__device__ __forceinline__ ull pk(float lo, float hi) {
    ull r; asm("mov.b64 %0,{%1,%2};" : "=l"(r) : "f"(lo), "f"(hi)); return r;
}
__device__ __forceinline__ void fma2(ull &a, ull x, ull y) {
    asm("fma.rn.f32x2 %0,%1,%2,%3;" : "=l"(a) : "l"(x), "l"(y), "l"(a));
}
__device__ __forceinline__ float psum(ull a) {
    float lo, hi; asm("mov.b64 {%0,%1},%2;" : "=f"(lo), "=f"(hi) : "l"(a)); return lo + hi;
}
__device__ __forceinline__ float selu_f(float x) {
    const float s  = 1.0507009873554805f;
    const float sa = 1.7580993408473766f;
    float e = __expf(x);
    return x > 0.f ? s * x : sa * e - sa;
}
__device__ __forceinline__ u32 swz(u32 b) { return b ^ ((b >> 3) & 0x70); }

__device__ __forceinline__ u32 s2u(const void* p) {
    u32 a;
    asm("{ .reg .u64 t; cvta.to.shared.u64 t,%1; cvt.u32.u64 %0,t; }" : "=r"(a) : "l"(p));
    return a;
}

#if USE_TC
__device__ __forceinline__ bool elect1() {
    u32 p;
    asm volatile("{ .reg .pred p; elect.sync _|p, 0xFFFFFFFF; selp.b32 %0,1,0,p; }" : "=r"(p));
    return p != 0;
}
__device__ __forceinline__ ull mkdesc(u32 a) {
    return 0x4000404000010000ULL | ((ull)(a >> 4) & 0x3FFFULL);
}
__device__ __forceinline__ void mma_ss(u32 d, ull ad, ull bd, u32 idesc, u32 en) {
    asm volatile(
        "{\n\t.reg .pred p;\n\tsetp.ne.u32 p,%4,0;\n\t"
        "tcgen05.mma.cta_group::1.kind::f16 [%0], %1, %2, %3, {%5,%5,%5,%5}, p;\n\t}"
        :: "r"(d), "l"(ad), "l"(bd), "r"(idesc), "r"(en), "r"(0u) : "memory");
}
__device__ __forceinline__ void tc_commit(u32 mbar) {
    asm volatile("tcgen05.commit.cta_group::1.mbarrier::arrive::one.shared::cluster.b64 [%0];"
                 :: "r"(mbar) : "memory");
}
__device__ __forceinline__ void mbar_wait(u32 m, u32 parity) {
    asm volatile(
        "{\n\t.reg .pred P;\n\t"
        "WL_%=:\n\t"
        "mbarrier.try_wait.parity.acquire.cta.shared::cta.b64 P,[%0],%1,0x989680;\n\t"
        "@P bra.uni WD_%=;\n\t"
        "bra.uni WL_%=;\n\t"
        "WD_%=:\n\t}"
        :: "r"(m), "r"(parity) : "memory");
}
__device__ __forceinline__ void ldtm32(u32* r, u32 a) {
    asm volatile(
        "tcgen05.ld.sync.aligned.32x32b.x32.b32 "
        "{%0,%1,%2,%3,%4,%5,%6,%7,%8,%9,%10,%11,%12,%13,%14,%15,"
        "%16,%17,%18,%19,%20,%21,%22,%23,%24,%25,%26,%27,%28,%29,%30,%31},[%32];"
        : "=r"(r[0]),"=r"(r[1]),"=r"(r[2]),"=r"(r[3]),"=r"(r[4]),"=r"(r[5]),"=r"(r[6]),"=r"(r[7]),
          "=r"(r[8]),"=r"(r[9]),"=r"(r[10]),"=r"(r[11]),"=r"(r[12]),"=r"(r[13]),"=r"(r[14]),"=r"(r[15]),
          "=r"(r[16]),"=r"(r[17]),"=r"(r[18]),"=r"(r[19]),"=r"(r[20]),"=r"(r[21]),"=r"(r[22]),"=r"(r[23]),
          "=r"(r[24]),"=r"(r[25]),"=r"(r[26]),"=r"(r[27]),"=r"(r[28]),"=r"(r[29]),"=r"(r[30]),"=r"(r[31])
        : "r"(a));
}
__device__ __forceinline__ void ldtm8(u32* r, u32 a) {
    asm volatile(
        "tcgen05.ld.sync.aligned.32x32b.x8.b32 {%0,%1,%2,%3,%4,%5,%6,%7},[%8];"
        : "=r"(r[0]),"=r"(r[1]),"=r"(r[2]),"=r"(r[3]),"=r"(r[4]),"=r"(r[5]),"=r"(r[6]),"=r"(r[7])
        : "r"(a));
}
__device__ __forceinline__ void tc_waitld() {
    asm volatile("tcgen05.wait::ld.sync.aligned;" ::: "memory");
}
#endif  // USE_TC

// ---------------------------------------------------------------------------
// prep kernel: convert F weights to pre-swizzled bf16 hi/lo SMEM images.
// Blob: L0 @0 (4 x 8192), L1 @32768 (4 x 32768), L2 @163840 (4 x 32768),
//       L3 @294912 (8192 = 16 rows x 256, rows 6..15 zero).
// ---------------------------------------------------------------------------
__global__ void prep_kernel(const float* __restrict__ fw0, const float* __restrict__ fw1,
                            const float* __restrict__ fw2, const float* __restrict__ fw3)
{
    int idx = blockIdx.x * 256 + threadIdx.x;
    if (idx >= 143360) return;
    float val; u32 base, off;
    if (idx < 8192) {                    // L0: 256 x 32
        int row = idx >> 5, col = idx & 31;
        val = fw0[idx];
        int ch = row >> 6, r = row & 63;
        base = 0u + (u32)ch * 8192u;
        off  = swz((u32)(r >> 3) * 1024u + (u32)(r & 7) * 128u + (u32)col * 2u);
    } else if (idx < 73728) {            // L1: 256 x 256
        int i2 = idx - 8192;
        int row = i2 >> 8, col = i2 & 255;
        val = fw1[i2];
        int ch = row >> 6, r = row & 63;
        base = 32768u + (u32)ch * 32768u;
        off  = swz((u32)(r >> 3) * 1024u + (u32)(col >> 6) * 8192u + (u32)(r & 7) * 128u + (u32)(col & 63) * 2u);
    } else if (idx < 139264) {           // L2: 256 x 256
        int i2 = idx - 73728;
        int row = i2 >> 8, col = i2 & 255;
        val = fw2[i2];
        int ch = row >> 6, r = row & 63;
        base = 163840u + (u32)ch * 32768u;
        off  = swz((u32)(r >> 3) * 1024u + (u32)(col >> 6) * 8192u + (u32)(r & 7) * 128u + (u32)(col & 63) * 2u);
    } else {                             // L3: 16 x 256 (rows 6..15 zero pad)
        int i2 = idx - 139264;
        int row = i2 >> 8, col = i2 & 255;
        val = (row < 6) ? fw3[row * 256 + col] : 0.f;
        base = 294912u;
        off  = swz((u32)(row >> 3) * 1024u + (u32)(col >> 6) * 2048u + (u32)(row & 7) * 128u + (u32)(col & 63) * 2u);
    }
    __nv_bfloat16 hi = __float2bfloat16(val);
    __nv_bfloat16 lo = __float2bfloat16(val - __bfloat162float(hi));
    *(__nv_bfloat16*)(g_wb + base + off) = hi;
    *(__nv_bfloat16*)(g_wb + WB_LO_OFF + base + off) = lo;
}

// ---------------------------------------------------------------------------
// G kernel (unchanged): recurrent statevar evolution.
// ---------------------------------------------------------------------------
__global__ void __launch_bounds__(256, 1) g_kernel(
    const float* __restrict__ x,
    const float* __restrict__ gw0, const float* __restrict__ gb0,
    const float* __restrict__ gw1, const float* __restrict__ gb1,
    const float* __restrict__ gw2, const float* __restrict__ gb2,
    const float* __restrict__ gw3, const float* __restrict__ gb3)
{
    extern __shared__ float sm[];
    float* s_eps = sm;
    float* s_dt  = sm + 11988;
    float* s_h0  = sm + 13986;
    float* s_h1  = sm + 14114;
    float* s_h2  = sm + 14370;
    float* s_sv  = sm + 14498;

    const int tid = threadIdx.x;
    const int bid = blockIdx.x;
    const int b0g = 2 * bid;

    for (int i = tid; i < 2 * TST * 6; i += 256) {
        int e = i / (TST * 6);
        int r = i - e * (TST * 6);
        int t = r / 6, f = r - t * 6;
        s_eps[i] = x[(size_t)(b0g + e) * (SSZ * 13) + t * 13 + 1 + f];
    }
    for (int i = tid; i < 2 * TST; i += 256) {
        int e = i / TST, t = i - e * TST;
        const float* xb = x + (size_t)(b0g + e) * (SSZ * 13);
        s_dt[i] = xb[(t + 1) * 13] - xb[t * 13];
    }
    if (tid < 2 * NSV) {
        int e = tid / NSV, o = tid - e * NSV;
        s_sv[tid] = 0.f;
        g_sv[(size_t)(b0g + e) * (SSZ * NSV) + o] = 0.f;
    }
    __syncthreads();

    if (tid < 128) {
        const int j = tid;
        ull w0p[13], w1p[64];
        #pragma unroll
        for (int i = 0; i < 13; i++) {
            float2 v = *(const float2*)(gw0 + j * 26 + 2 * i);
            w0p[i] = pk(v.x, v.y);
        }
        #pragma unroll
        for (int i = 0; i < 64; i++) {
            float2 v = *(const float2*)(gw1 + j * 128 + 2 * i);
            w1p[i] = pk(v.x, v.y);
        }
        const float b0 = gb0[j], b1 = gb1[j];

        for (int n = 0; n < 2 * TST + 1; ++n) {
            if (n < 2 * TST) {
                const int e = n & 1, t = n >> 1;
                const ull* ep = (const ull*)(s_eps + e * (TST * 6) + t * 6);
                const ull* sp = (const ull*)(s_sv + e * NSV);
                ull aa = pk(b0, 0.f), ab = 0ull;
                fma2(aa, w0p[0], ep[0]);
                fma2(ab, w0p[1], ep[1]);
                fma2(aa, w0p[2], ep[2]);
                #pragma unroll
                for (int i = 0; i < 10; i += 2) {
                    fma2(ab, w0p[3 + i], sp[i]);
                    fma2(aa, w0p[4 + i], sp[i + 1]);
                }
                s_h0[j] = selu_f(psum(aa) + psum(ab));
                asm volatile("bar.sync 1, 128;" ::: "memory");
                const ull* hp = (const ull*)s_h0;
                ull ca = pk(b1, 0.f), cb = 0ull;
                #pragma unroll
                for (int i = 0; i < 64; i += 2) {
                    fma2(ca, w1p[i],     hp[i]);
                    fma2(cb, w1p[i + 1], hp[i + 1]);
                }
                s_h1[e * 128 + j] = selu_f(psum(ca) + psum(cb));
            }
            asm volatile("bar.sync 0;" ::: "memory");
        }
    } else {
        const int j  = tid - 128;
        const int oc = j >> 2;
        const int o  = (oc < NSV) ? oc : 0;
        const int p  = j & 3;
        const bool act = (p == 0) && (oc < NSV);
        ull w2p[64], w3p[16];
        #pragma unroll
        for (int i = 0; i < 64; i++) {
            float2 v = *(const float2*)(gw2 + j * 128 + 2 * i);
            w2p[i] = pk(v.x, v.y);
        }
        #pragma unroll
        for (int i = 0; i < 16; i++) {
            float2 v = *(const float2*)(gw3 + o * 128 + p * 32 + 2 * i);
            w3p[i] = pk(v.x, v.y);
        }
        const float b2 = gb2[j], b3 = gb3[o];

        for (int n = 0; n < 2 * TST + 1; ++n) {
            if (n >= 1) {
                const int e = (n - 1) & 1, t = (n - 1) >> 1;
                const ull* hp = (const ull*)(s_h1 + e * 128);
                ull ca = pk(b2, 0.f), cb = 0ull;
                #pragma unroll
                for (int i = 0; i < 64; i += 2) {
                    fma2(ca, w2p[i],     hp[i]);
                    fma2(cb, w2p[i + 1], hp[i + 1]);
                }
                s_h2[j] = selu_f(psum(ca) + psum(cb));
                asm volatile("bar.sync 2, 128;" ::: "memory");
                const ull* h2p = (const ull*)(s_h2 + p * 32);
                ull da = 0ull, db = 0ull;
                #pragma unroll
                for (int i = 0; i < 16; i += 2) {
                    fma2(da, w3p[i],     h2p[i]);
                    fma2(db, w3p[i + 1], h2p[i + 1]);
                }
                float v = psum(da) + psum(db);
                v += __shfl_down_sync(0xffffffffu, v, 1);
                v += __shfl_down_sync(0xffffffffu, v, 2);
                if (act) {
                    float svd = v + b3;
                    float nsv = s_sv[e * NSV + o] + s_dt[e * TST + t] * svd;
                    s_sv[e * NSV + o] = nsv;
                    g_sv[(size_t)(b0g + e) * (SSZ * NSV) + (t + 1) * NSV + o] = nsv;
                }
            }
            asm volatile("bar.sync 0;" ::: "memory");
        }
    }
}

// ---------------------------------------------------------------------------
// fp32 fallback layer routine (used by non-sm_103a compile passes)
// ---------------------------------------------------------------------------
#define FSTR 258
#define WSTR 34

__device__ __forceinline__ void mlayer(
    const float* sIn, float* sOut, float* sW, float* sb,
    const float* __restrict__ Wg, const float* __restrict__ bg,
    int K, int tid)
{
    const int rb = (tid >> 4) * 4;
    const int m  = tid & 15;
    ull acc[4][16];
    #pragma unroll
    for (int r = 0; r < 4; r++)
        #pragma unroll
        for (int c = 0; c < 16; c++) acc[r][c] = 0ull;

    for (int c0 = 0; c0 < K; c0 += 32) {
        __syncthreads();
        if (c0 == 0) sb[tid] = bg[tid];
        for (int it = tid; it < 2048; it += 256) {
            int c = it >> 3, q = it & 7;
            float4 v = *(const float4*)(Wg + c * K + c0 + 4 * q);
            float2* d = (float2*)(sW + c * WSTR + 4 * q);
            d[0] = make_float2(v.x, v.y);
            d[1] = make_float2(v.z, v.w);
        }
        __syncthreads();
        const ull* ap0 = (const ull*)(sIn + (rb + 0) * FSTR + c0);
        const ull* ap1 = (const ull*)(sIn + (rb + 1) * FSTR + c0);
        const ull* ap2 = (const ull*)(sIn + (rb + 2) * FSTR + c0);
        const ull* ap3 = (const ull*)(sIn + (rb + 3) * FSTR + c0);
        #pragma unroll
        for (int i = 0; i < 16; ++i) {
            ull a0 = ap0[i], a1 = ap1[i], a2 = ap2[i], a3 = ap3[i];
            #pragma unroll
            for (int ci = 0; ci < 16; ++ci) {
                ull w = *(const ull*)(sW + (m + 16 * ci) * WSTR + 2 * i);
                fma2(acc[0][ci], a0, w);
                fma2(acc[1][ci], a1, w);
                fma2(acc[2][ci], a2, w);
                fma2(acc[3][ci], a3, w);
            }
        }
    }
    #pragma unroll
    for (int r = 0; r < 4; r++) {
        #pragma unroll
        for (int ci = 0; ci < 16; ci++) {
            int c = m + 16 * ci;
            float v = psum(acc[r][ci]) + sb[c];
            sOut[(rb + r) * FSTR + c] = selu_f(v);
        }
    }
}

// ---------------------------------------------------------------------------
// F kernel: fused 32->256->256->256->6 MLP, 128 rows per CTA, grid=2000.
// sm_103a pass: tcgen05 bf16 hi/lo compensated MMA (fp32 TMEM accumulate).
// other passes: fp32 f32x2 register-tiled fallback (two 64-row passes).
// ---------------------------------------------------------------------------
#define SM_AH   0u
#define SM_AL   65536u
#define SM_BH   131072u
#define SM_BL   163840u
#define SM_SB   196608u
#define SM_CTRL 199712u
#define SM_MBAR 199720u
#define F_SMEM  (1024 + 199728 + 16)

__global__ void __launch_bounds__(256, 1) f_kernel(
    const float* __restrict__ x,
    const float* __restrict__ fw0, const float* __restrict__ fb0,
    const float* __restrict__ fw1, const float* __restrict__ fb1,
    const float* __restrict__ fw2, const float* __restrict__ fb2,
    const float* __restrict__ fw3, const float* __restrict__ fb3,
    float* __restrict__ out)
{
#if USE_TC
    extern __shared__ unsigned char smraw[];
    u32 raw  = s2u(smraw);
    u32 base = (raw + 1023u) & ~1023u;
    unsigned char* smb = smraw + (base - raw);
    float* sbias = (float*)(smb + SM_SB);

    const int tid = threadIdx.x;
    const int w   = tid >> 5;
    const int lid = tid & 31;
    const int row0 = blockIdx.x * 128;

    if (w == 0) {
        asm volatile("tcgen05.alloc.cta_group::1.sync.aligned.shared::cta.b32 [%0], %1;"
                     :: "r"(base + SM_CTRL), "r"(256) : "memory");
        asm volatile("tcgen05.relinquish_alloc_permit.cta_group::1.sync.aligned;");
    }
    if (tid == 0) {
        asm volatile("mbarrier.init.shared.b64 [%0], 1;" :: "r"(base + SM_MBAR) : "memory");
    }
    // biases
    sbias[tid]       = fb0[tid];
    sbias[256 + tid] = fb1[tid];
    sbias[512 + tid] = fb2[tid];
    if (tid < 8) sbias[768 + tid] = (tid < 6) ? fb3[tid] : 0.f;

    // stage layer-0 input: 128 rows x 32 cols (12 strain/strain_dot + 20 sv)
    for (int v = tid; v < 128 * 32; v += 256) {
        int r = v >> 5, c = v & 31;
        float val = (c < 12) ? x[(size_t)(row0 + r) * 13 + 1 + c]
                             : g_sv[(size_t)(row0 + r) * 20 + (c - 12)];
        __nv_bfloat16 hi = __float2bfloat16(val);
        __nv_bfloat16 lo = __float2bfloat16(val - __bfloat162float(hi));
        u32 off = swz((u32)(r >> 3) * 1024u + (u32)(r & 7) * 128u + (u32)c * 2u);
        *(__nv_bfloat16*)(smb + SM_AH + off) = hi;
        *(__nv_bfloat16*)(smb + SM_AL + off) = lo;
    }
    __syncthreads();

    u32 tmem;
    asm volatile("ld.shared.b32 %0,[%1];" : "=r"(tmem) : "r"(base + SM_CTRL));

    const ull adh = mkdesc(base + SM_AH), adl = mkdesc(base + SM_AL);
    const ull bdh = mkdesc(base + SM_BH), bdl = mkdesc(base + SM_BL);

    const u32 wb_base[4] = {0u, 32768u, 163840u, 294912u};
    const int chunkB[4]  = {8192, 32768, 32768, 8192};
    const int nch[4]     = {4, 4, 4, 1};
    const int ks[4]      = {2, 16, 16, 16};
    const int bblk[4]    = {512, 512, 512, 128};  // 16B units per 64-col atom block of B
    const int nn[4]      = {64, 64, 64, 16};

    int ph = 0;
    for (int L = 0; L < 4; ++L) {
        for (int n = 0; n < nch[L]; ++n) {
            // copy pre-swizzled B chunk (hi + lo)
            const uint4* srcH = (const uint4*)(g_wb + wb_base[L] + (size_t)n * chunkB[L]);
            const uint4* srcL = (const uint4*)(g_wb + WB_LO_OFF + wb_base[L] + (size_t)n * chunkB[L]);
            uint4* dH = (uint4*)(smb + SM_BH);
            uint4* dL = (uint4*)(smb + SM_BL);
            int nv = chunkB[L] >> 4;
            for (int i = tid; i < nv; i += 256) { dH[i] = srcH[i]; dL[i] = srcL[i]; }
            asm volatile("fence.proxy.async.shared::cta;" ::: "memory");
            __syncthreads();

            if (w == 0) {
                asm volatile("tcgen05.fence::after_thread_sync;" ::: "memory");
                if (elect1()) {
                    u32 idesc = 0x490u | ((u32)(nn[L] / 8) << 17) | (8u << 24);
                    u32 dcol  = tmem + n * 64;
                    u32 en = 0;
                    #pragma unroll 1
                    for (int term = 0; term < 3; ++term) {
                        ull ad = (term == 2) ? adl : adh;
                        ull bd = (term == 1) ? bdl : bdh;
                        for (int s = 0; s < ks[L]; ++s) {
                            ull adk = ad + (ull)((s >> 2) * 1024 + (s & 3) * 2);
                            ull bdk = bd + (ull)((s >> 2) * bblk[L] + (s & 3) * 2);
                            mma_ss(dcol, adk, bdk, idesc, en);
                            en = 1;
                        }
                    }
                    tc_commit(base + SM_MBAR);
                }
            }
            mbar_wait(base + SM_MBAR, (u32)(ph & 1));
            ph++;
        }
        asm volatile("tcgen05.fence::after_thread_sync;" ::: "memory");

        if (L < 3) {
            // epilogue: bias + selu + bf16 hi/lo split -> A tile (K=256 layout)
            const int cb = (w >> 2) * 128;       // warps 0-3: cols 0-127, warps 4-7: 128-255
            const int bo = L * 256;
            const int r  = (w & 3) * 32 + lid;
            for (int cc = 0; cc < 4; ++cc) {
                int c0 = cb + cc * 32;
                u32 d[32];
                ldtm32(d, tmem + c0);
                tc_waitld();
                #pragma unroll
                for (int g = 0; g < 4; ++g) {
                    int cg = c0 + g * 8;
                    u32 hp[4], lp[4];
                    #pragma unroll
                    for (int k2 = 0; k2 < 4; ++k2) {
                        float v0 = __uint_as_float(d[g * 8 + 2 * k2])     + sbias[bo + cg + 2 * k2];
                        float v1 = __uint_as_float(d[g * 8 + 2 * k2 + 1]) + sbias[bo + cg + 2 * k2 + 1];
                        float s0 = selu_f(v0), s1 = selu_f(v1);
                        __nv_bfloat16 h0 = __float2bfloat16(s0), h1 = __float2bfloat16(s1);
                        __nv_bfloat16 l0 = __float2bfloat16(s0 - __bfloat162float(h0));
                        __nv_bfloat16 l1 = __float2bfloat16(s1 - __bfloat162float(h1));
                        hp[k2] = (u32)__bfloat16_as_ushort(h0) | ((u32)__bfloat16_as_ushort(h1) << 16);
                        lp[k2] = (u32)__bfloat16_as_ushort(l0) | ((u32)__bfloat16_as_ushort(l1) << 16);
                    }
                    u32 off = swz((u32)(r >> 3) * 1024u + (u32)(cg >> 6) * 16384u +
                                  (u32)(r & 7) * 128u + (u32)(cg & 63) * 2u);
                    *(uint4*)(smb + SM_AH + off) = make_uint4(hp[0], hp[1], hp[2], hp[3]);
                    *(uint4*)(smb + SM_AL + off) = make_uint4(lp[0], lp[1], lp[2], lp[3]);
                }
            }
            asm volatile("tcgen05.fence::before_thread_sync;" ::: "memory");
            asm volatile("fence.proxy.async.shared::cta;" ::: "memory");
            __syncthreads();
        }
    }

    // final epilogue: 6 outputs per row
    if (w < 4) {
        u32 d8[8];
        ldtm8(d8, tmem);
        tc_waitld();
        int r = w * 32 + lid;
        #pragma unroll
        for (int c = 0; c < 6; ++c)
            out[(size_t)(row0 + r) * 6 + c] = __uint_as_float(d8[c]) + sbias[768 + c];
    }
    asm volatile("tcgen05.fence::before_thread_sync;" ::: "memory");
    __syncthreads();
    if (w == 0) {
        asm volatile("tcgen05.dealloc.cta_group::1.sync.aligned.b32 %0, %1;" :: "r"(tmem), "r"(256));
    }
#else
    // ---------------- fp32 fallback: two 64-row passes ----------------
    extern __shared__ float smf[];
    float* sA  = smf;            // 64 * 258 = 16512
    float* sB  = smf + 16512;    // 16512
    float* sW  = smf + 33024;    // 256 * 34 = 8704
    float* sW3 = smf + 41728;    // 6 * 258 = 1548
    float* sb  = smf + 43276;    // 256

    const int tid = threadIdx.x;

    // stage W3 (6 x 256), stride 258 (once)
    for (int i = tid; i < 6 * 64; i += 256) {
        int c = i >> 6, q = i & 63;
        float4 v = *(const float4*)(fw3 + c * 256 + 4 * q);
        float2* d = (float2*)(sW3 + c * FSTR + 4 * q);
        d[0] = make_float2(v.x, v.y);
        d[1] = make_float2(v.z, v.w);
    }

    for (int half = 0; half < 2; ++half) {
        const int row0 = blockIdx.x * 128 + half * 64;
        __syncthreads();
        for (int i = tid; i < 64 * 12; i += 256) {
            int r = i / 12, f = i - r * 12;
            sA[r * FSTR + f] = x[(size_t)(row0 + r) * 13 + 1 + f];
        }
        for (int i = tid; i < 64 * 20; i += 256) {
            int r = i / 20, f = i - r * 20;
            sA[r * FSTR + 12 + f] = g_sv[(size_t)(row0 + r) * 20 + f];
        }

        mlayer(sA, sB, sW, sb, fw0, fb0, 32,  tid);
        mlayer(sB, sA, sW, sb, fw1, fb1, 256, tid);
        mlayer(sA, sB, sW, sb, fw2, fb2, 256, tid);
        __syncthreads();

        const int r = tid >> 2, p = tid & 3;
        ull a3[6];
        #pragma unroll
        for (int c = 0; c < 6; c++) a3[c] = 0ull;
        const ull* ap = (const ull*)(sB + r * FSTR + 64 * p);
        #pragma unroll
        for (int i = 0; i < 32; ++i) {
            ull a = ap[i];
            #pragma unroll
            for (int c = 0; c < 6; c++) {
                ull wv = *(const ull*)(sW3 + c * FSTR + 64 * p + 2 * i);
                fma2(a3[c], a, wv);
            }
        }
        #pragma unroll
        for (int c = 0; c < 6; c++) {
            float v = psum(a3[c]);
            v += __shfl_down_sync(0xffffffffu, v, 1);
            v += __shfl_down_sync(0xffffffffu, v, 2);
            if (p == 0) out[(size_t)(row0 + r) * 6 + c] = v + fb3[c];
        }
        __syncthreads();
    }
#endif
}

// ---------------------------------------------------------------------------
extern "C" void kernel_launch(void* const* d_in, const int* in_sizes, int n_in,
                              void* d_out, int out_size)
{
    (void)in_sizes; (void)n_in; (void)out_size;
    const float* x   = (const float*)d_in[0];
    const float* gw0 = (const float*)d_in[1];
    const float* gb0 = (const float*)d_in[2];
    const float* gw1 = (const float*)d_in[3];
    const float* gb1 = (const float*)d_in[4];
    const float* gw2 = (const float*)d_in[5];
    const float* gb2 = (const float*)d_in[6];
    const float* gw3 = (const float*)d_in[7];
    const float* gb3 = (const float*)d_in[8];
    const float* fw0 = (const float*)d_in[9];
    const float* fb0 = (const float*)d_in[10];
    const float* fw1 = (const float*)d_in[11];
    const float* fb1 = (const float*)d_in[12];
    const float* fw2 = (const float*)d_in[13];
    const float* fb2 = (const float*)d_in[14];
    const float* fw3 = (const float*)d_in[15];
    const float* fb3 = (const float*)d_in[16];

    const size_t gsm = 14538 * sizeof(float);
    cudaFuncSetAttribute(g_kernel, cudaFuncAttributeMaxDynamicSharedMemorySize, (int)gsm);
    cudaFuncSetAttribute(f_kernel, cudaFuncAttributeMaxDynamicSharedMemorySize, F_SMEM);

    prep_kernel<<<560, 256>>>(fw0, fw1, fw2, fw3);
    g_kernel<<<128, 256, gsm>>>(x, gw0, gb0, gw1, gb1, gw2, gb2, gw3, gb3);
    f_kernel<<<2000, 256, F_SMEM>>>(x, fw0, fb0, fw1, fb1, fw2, fb2, fw3, fb3,
                                    (float*)d_out);
}